// round 8
// baseline (speedup 1.0000x reference)
#include <cuda_runtime.h>
#include <math.h>

#define N_NODES 50000
#define N_EDGES 800000

#define INV_SQRT8  0.35355339059327373f
#define INV_SQRT32 0.17677669529663687f
#define CG_INV3    0.5773502691896258f   // 1/sqrt(3)
#define CG_INV2    0.7071067811865476f   // 1/sqrt(2)
#define MS_SCALE   0.125f                // 1/sqrt(64)
#define MV_SCALE   0.10206207261596575f  // 1/sqrt(96)
#define NSC_SCALE  0.0625f               // 1/sqrt(256)
#define NEIGH_INV  0.25f                 // 1/sqrt(16)

// Scratch (static device memory — no allocation in kernel_launch)
__device__ __align__(16) float g_xs[N_NODES * 32];    // linear_1 scalar out
__device__ __align__(16) float g_xv[N_NODES * 96];    // linear_1 vector out, [N][3][32] comp-major
__device__ __align__(16) float g_aggs[N_NODES * 64];  // aggregated scalars, [N][64]
__device__ __align__(16) float g_aggv[N_NODES * 288]; // aggregated vectors, [N][3][96] comp-major
// CSR-by-destination scratch
__device__ int g_cnt[N_NODES];
__device__ int g_off[N_NODES + 1];
__device__ int g_cur[N_NODES];
__device__ int g_elist[N_EDGES];

// ---------------------------------------------------------------------------
// CSR build: zero counts -> count -> scan -> fill
// ---------------------------------------------------------------------------
__global__ void zero_cnt_kernel() {
    int i = blockIdx.x * blockDim.x + threadIdx.x;
    if (i < N_NODES) g_cnt[i] = 0;
}

__global__ void count_kernel(const int* __restrict__ dst) {
    int e = blockIdx.x * blockDim.x + threadIdx.x;
    if (e < N_EDGES) atomicAdd(&g_cnt[dst[e]], 1);
}

__global__ void scan_kernel() {
    // single block, 1024 threads; chunked exclusive prefix sum over 50000
    __shared__ int part[1024];
    const int CH = (N_NODES + 1023) / 1024;   // 49
    const int t = threadIdx.x;
    const int lo = t * CH;
    const int hi = min(lo + CH, N_NODES);
    int s = 0;
    for (int i = lo; i < hi; i++) s += g_cnt[i];
    part[t] = s;
    __syncthreads();
    if (t == 0) {
        int run = 0;
        for (int i = 0; i < 1024; i++) { int tmp = part[i]; part[i] = run; run += tmp; }
    }
    __syncthreads();
    int run = part[t];
    for (int i = lo; i < hi; i++) {
        g_off[i] = run;
        g_cur[i] = run;
        run += g_cnt[i];
    }
    if (t == 0) g_off[N_NODES] = N_EDGES;
}

__global__ void fill_kernel(const int* __restrict__ dst) {
    int e = blockIdx.x * blockDim.x + threadIdx.x;
    if (e < N_EDGES) {
        int p = atomicAdd(&g_cur[dst[e]], 1);
        g_elist[p] = e;
    }
}

// ---------------------------------------------------------------------------
// linear_1 (per-l equivariant channel mixing), one warp per node
// ---------------------------------------------------------------------------
__global__ void lin1_kernel(const float* __restrict__ node_s,
                            const float* __restrict__ node_v,
                            const float* __restrict__ W1s,
                            const float* __restrict__ W1v) {
    __shared__ float sW1s[1024];
    __shared__ float sW1v[1024];
    for (int i = threadIdx.x; i < 1024; i += blockDim.x) {
        sW1s[i] = W1s[i];
        sW1v[i] = W1v[i];
    }
    __syncthreads();

    const int warp = (blockIdx.x * blockDim.x + threadIdx.x) >> 5;
    const int lane = threadIdx.x & 31;
    if (warp >= N_NODES) return;
    const int n = warp;

    float sl = node_s[n * 32 + lane];
    float acc = 0.f;
#pragma unroll
    for (int u = 0; u < 32; u++)
        acc += __shfl_sync(0xffffffffu, sl, u) * sW1s[u * 32 + lane];
    g_xs[n * 32 + lane] = acc * INV_SQRT32;

#pragma unroll
    for (int c = 0; c < 3; c++) {
        float vl = node_v[n * 96 + lane * 3 + c];
        float a = 0.f;
#pragma unroll
        for (int u = 0; u < 32; u++)
            a += __shfl_sync(0xffffffffu, vl, u) * sW1v[u * 32 + lane];
        g_xv[n * 96 + c * 32 + lane] = a * INV_SQRT32;
    }
}

// ---------------------------------------------------------------------------
// Node-centric gather + radial MLP + CG tensor product. NO ATOMICS.
// 8 threads per node; thread `sub` owns channels [4*sub, 4*sub+3].
// Loops over the node's incident edges (CSR), accumulates in registers,
// stores with plain STG at the end.
// ---------------------------------------------------------------------------
__global__ __launch_bounds__(256) void gather_tp_kernel(
        const float* __restrict__ emb,
        const float* __restrict__ sh0,
        const float* __restrict__ sh1,
        const int*   __restrict__ src,
        const float* __restrict__ Wm1,
        const float* __restrict__ Wm2) {
    __shared__ float sWm1[64];
    __shared__ float sWm2[1280];
    const float wscale = INV_SQRT8 * NEIGH_INV;   // fold 1/sqrt(HID), 1/sqrt(avg_neigh)
    for (int i = threadIdx.x; i < 64; i += blockDim.x) sWm1[i] = Wm1[i];
    for (int i = threadIdx.x; i < 1280; i += blockDim.x) sWm2[i] = Wm2[i] * wscale;
    __syncthreads();

    const int gt = blockIdx.x * blockDim.x + threadIdx.x;
    const int n = gt >> 3;
    if (n >= N_NODES) return;
    const int sub = gt & 7;
    const int u0 = sub * 4;
    const unsigned lane = threadIdx.x & 31u;
    const unsigned gmask = 0xFFu << (lane & 24u);   // this thread's 8-lane group

    const int beg = g_off[n];
    const int end = g_off[n + 1];

    float aP1[4], aP2[4], aP3[3][4], aP4[3][4], aP5[3][4];
#pragma unroll
    for (int j = 0; j < 4; j++) { aP1[j] = 0.f; aP2[j] = 0.f; }
#pragma unroll
    for (int c = 0; c < 3; c++)
#pragma unroll
        for (int j = 0; j < 4; j++) { aP3[c][j] = 0.f; aP4[c][j] = 0.f; aP5[c][j] = 0.f; }

    for (int i = beg; i < end; i++) {
        const int e = __ldg(&g_elist[i]);

        // ---- radial MLP (8-wide across the group) ----
        float embv = emb[e * 8 + sub];
        float hacc = 0.f;
#pragma unroll
        for (int k = 0; k < 8; k++)
            hacc += __shfl_sync(gmask, embv, k, 8) * sWm1[k * 8 + sub];
        hacc *= INV_SQRT8;
        const float h = hacc / (1.f + expf(-hacc));   // silu

        float w[5][4];
#pragma unroll
        for (int p = 0; p < 5; p++)
#pragma unroll
            for (int j = 0; j < 4; j++) w[p][j] = 0.f;
#pragma unroll
        for (int k = 0; k < 8; k++) {
            const float hk = __shfl_sync(gmask, h, k, 8);
            const float* wrow = &sWm2[k * 160 + u0];
#pragma unroll
            for (int p = 0; p < 5; p++)
#pragma unroll
                for (int j = 0; j < 4; j++)
                    w[p][j] += hk * wrow[p * 32 + j];
        }

        // ---- gather source features (L2-resident scratch) ----
        const int ns = __ldg(&src[e]);
        const float q0  = __ldg(&sh0[e]);
        const float s1x = __ldg(&sh1[e * 3 + 0]);
        const float s1y = __ldg(&sh1[e * 3 + 1]);
        const float s1z = __ldg(&sh1[e * 3 + 2]);

        const float4 S  = *reinterpret_cast<const float4*>(g_xs + ns * 32 + u0);
        const float4 VX = *reinterpret_cast<const float4*>(g_xv + ns * 96 + u0);
        const float4 VY = *reinterpret_cast<const float4*>(g_xv + ns * 96 + 32 + u0);
        const float4 VZ = *reinterpret_cast<const float4*>(g_xv + ns * 96 + 64 + u0);
        const float s_[4] = {S.x, S.y, S.z, S.w};
        const float vx[4] = {VX.x, VX.y, VX.z, VX.w};
        const float vy[4] = {VY.x, VY.y, VY.z, VY.w};
        const float vz[4] = {VZ.x, VZ.y, VZ.z, VZ.w};

#pragma unroll
        for (int j = 0; j < 4; j++) {
            const float dot = vx[j] * s1x + vy[j] * s1y + vz[j] * s1z;
            const float cx = vy[j] * s1z - vz[j] * s1y;
            const float cy = vz[j] * s1x - vx[j] * s1z;
            const float cz = vx[j] * s1y - vy[j] * s1x;
            aP1[j] += w[0][j] * s_[j] * q0;
            aP2[j] += w[1][j] * dot * CG_INV3;
            const float t3 = w[2][j] * s_[j];
            aP3[0][j] += t3 * s1x;
            aP3[1][j] += t3 * s1y;
            aP3[2][j] += t3 * s1z;
            const float t4 = w[3][j] * q0;
            aP4[0][j] += t4 * vx[j];
            aP4[1][j] += t4 * vy[j];
            aP4[2][j] += t4 * vz[j];
            const float t5 = w[4][j] * CG_INV2;
            aP5[0][j] += t5 * cx;
            aP5[1][j] += t5 * cy;
            aP5[2][j] += t5 * cz;
        }
    }

    // ---- plain stores (every element written; no zero-init pass needed) ----
    float* as_base = g_aggs + n * 64 + u0;
    *reinterpret_cast<float4*>(as_base)      = make_float4(aP1[0], aP1[1], aP1[2], aP1[3]);
    *reinterpret_cast<float4*>(as_base + 32) = make_float4(aP2[0], aP2[1], aP2[2], aP2[3]);
#pragma unroll
    for (int c = 0; c < 3; c++) {
        float* av_base = g_aggv + n * 288 + c * 96 + u0;
        *reinterpret_cast<float4*>(av_base)      = make_float4(aP3[c][0], aP3[c][1], aP3[c][2], aP3[c][3]);
        *reinterpret_cast<float4*>(av_base + 32) = make_float4(aP4[c][0], aP4[c][1], aP4[c][2], aP4[c][3]);
        *reinterpret_cast<float4*>(av_base + 64) = make_float4(aP5[c][0], aP5[c][1], aP5[c][2], aP5[c][3]);
    }
}

// ---------------------------------------------------------------------------
// Scalar output: agg_s @ W2s + scalar self-connection.
// 2 NODES x 8 CHANNELS per thread: each weight LDS.128 feeds 2x the FFMA.
// ---------------------------------------------------------------------------
__global__ __launch_bounds__(256) void node_s_kernel(
        const float* __restrict__ node_s,
        const float* __restrict__ attrs,
        const float* __restrict__ W2s,
        const float* __restrict__ Wscs,
        float* __restrict__ out) {
    extern __shared__ float sw[];
    float* sW2s  = sw;          // 2048 floats
    float* sWscs = sw + 2048;   // 8192 floats
    for (int i = threadIdx.x; i < 2048; i += blockDim.x)
        sW2s[i] = W2s[i] * MS_SCALE;
    for (int i = threadIdx.x; i < 8192; i += blockDim.x)
        sWscs[i] = Wscs[i] * NSC_SCALE;
    __syncthreads();

    const int gt = blockIdx.x * blockDim.x + threadIdx.x;
    const int pair = gt >> 2;
    if (pair >= N_NODES / 2) return;
    const int ch0 = (gt & 3) * 8;
    const int n0 = pair * 2;
    const int n1 = n0 + 1;

    float acc0[8], acc1[8];
#pragma unroll
    for (int j = 0; j < 8; j++) { acc0[j] = 0.f; acc1[j] = 0.f; }

    // m_s for both nodes
    const float4* inA = reinterpret_cast<const float4*>(g_aggs + n0 * 64);
    const float4* inB = reinterpret_cast<const float4*>(g_aggs + n1 * 64);
#pragma unroll 4
    for (int k4 = 0; k4 < 16; k4++) {
        const float4 av = inA[k4];
        const float4 bv = inB[k4];
        const float a[4] = {av.x, av.y, av.z, av.w};
        const float b[4] = {bv.x, bv.y, bv.z, bv.w};
#pragma unroll
        for (int j = 0; j < 4; j++) {
            const float4* wr = reinterpret_cast<const float4*>(sW2s + (k4 * 4 + j) * 32 + ch0);
            const float4 w0 = wr[0];
            const float4 w1 = wr[1];
            acc0[0] += a[j] * w0.x; acc0[1] += a[j] * w0.y;
            acc0[2] += a[j] * w0.z; acc0[3] += a[j] * w0.w;
            acc0[4] += a[j] * w1.x; acc0[5] += a[j] * w1.y;
            acc0[6] += a[j] * w1.z; acc0[7] += a[j] * w1.w;
            acc1[0] += b[j] * w0.x; acc1[1] += b[j] * w0.y;
            acc1[2] += b[j] * w0.z; acc1[3] += b[j] * w0.w;
            acc1[4] += b[j] * w1.x; acc1[5] += b[j] * w1.y;
            acc1[6] += b[j] * w1.z; acc1[7] += b[j] * w1.w;
        }
    }

    // sc_s for both nodes
    float at0[8], at1[8];
    {
        const float4 a0 = *reinterpret_cast<const float4*>(attrs + n0 * 8);
        const float4 a1 = *reinterpret_cast<const float4*>(attrs + n0 * 8 + 4);
        at0[0]=a0.x; at0[1]=a0.y; at0[2]=a0.z; at0[3]=a0.w;
        at0[4]=a1.x; at0[5]=a1.y; at0[6]=a1.z; at0[7]=a1.w;
        const float4 b0 = *reinterpret_cast<const float4*>(attrs + n1 * 8);
        const float4 b1 = *reinterpret_cast<const float4*>(attrs + n1 * 8 + 4);
        at1[0]=b0.x; at1[1]=b0.y; at1[2]=b0.z; at1[3]=b0.w;
        at1[4]=b1.x; at1[5]=b1.y; at1[6]=b1.z; at1[7]=b1.w;
    }
    const float4* nsA = reinterpret_cast<const float4*>(node_s + n0 * 32);
    const float4* nsB = reinterpret_cast<const float4*>(node_s + n1 * 32);
#pragma unroll 2
    for (int u4 = 0; u4 < 8; u4++) {
        const float4 sa = nsA[u4];
        const float4 sb = nsB[u4];
        const float sua[4] = {sa.x, sa.y, sa.z, sa.w};
        const float sub_[4] = {sb.x, sb.y, sb.z, sb.w};
#pragma unroll
        for (int j = 0; j < 4; j++) {
            const int u = u4 * 4 + j;
#pragma unroll
            for (int a = 0; a < 8; a++) {
                const float za = sua[j] * at0[a];
                const float zb = sub_[j] * at1[a];
                const float4* wr = reinterpret_cast<const float4*>(sWscs + (u * 8 + a) * 32 + ch0);
                const float4 w0 = wr[0];
                const float4 w1 = wr[1];
                acc0[0] += za * w0.x; acc0[1] += za * w0.y;
                acc0[2] += za * w0.z; acc0[3] += za * w0.w;
                acc0[4] += za * w1.x; acc0[5] += za * w1.y;
                acc0[6] += za * w1.z; acc0[7] += za * w1.w;
                acc1[0] += zb * w0.x; acc1[1] += zb * w0.y;
                acc1[2] += zb * w0.z; acc1[3] += zb * w0.w;
                acc1[4] += zb * w1.x; acc1[5] += zb * w1.y;
                acc1[6] += zb * w1.z; acc1[7] += zb * w1.w;
            }
        }
    }

    float4* o0 = reinterpret_cast<float4*>(out + n0 * 128 + ch0);
    o0[0] = make_float4(acc0[0], acc0[1], acc0[2], acc0[3]);
    o0[1] = make_float4(acc0[4], acc0[5], acc0[6], acc0[7]);
    float4* o1 = reinterpret_cast<float4*>(out + n1 * 128 + ch0);
    o1[0] = make_float4(acc1[0], acc1[1], acc1[2], acc1[3]);
    o1[1] = make_float4(acc1[4], acc1[5], acc1[6], acc1[7]);
}

// ---------------------------------------------------------------------------
// Vector output: agg_v @ W2v + vector self-connection.
// 2 NODES x 4 CHANNELS per thread; each weight LDS.128 serves 2 nodes
// (m_v additionally reuses it across the 3 components: 24 FFMA / LDS.128).
// ---------------------------------------------------------------------------
__global__ __launch_bounds__(256) void node_v_kernel(
        const float* __restrict__ node_v,
        const float* __restrict__ attrs,
        const float* __restrict__ W2v,
        const float* __restrict__ Wscv,
        float* __restrict__ out) {
    extern __shared__ float sw[];
    float* sW2v  = sw;          // 3072 floats
    float* sWscv = sw + 3072;   // 8192 floats
    for (int i = threadIdx.x; i < 3072; i += blockDim.x)
        sW2v[i] = W2v[i] * MV_SCALE;
    for (int i = threadIdx.x; i < 8192; i += blockDim.x)
        sWscv[i] = Wscv[i] * NSC_SCALE;
    __syncthreads();

    const int gt = blockIdx.x * blockDim.x + threadIdx.x;
    const int pair = gt >> 3;
    if (pair >= N_NODES / 2) return;
    const int ch0 = (gt & 7) * 4;
    const int n0 = pair * 2;
    const int n1 = n0 + 1;

    float accv0[3][4], accv1[3][4];
#pragma unroll
    for (int c = 0; c < 3; c++)
#pragma unroll
        for (int j = 0; j < 4; j++) { accv0[c][j] = 0.f; accv1[c][j] = 0.f; }

    // m_v: weight row loaded once per k, reused for 3 comps x 2 nodes
    const float4* iA0 = reinterpret_cast<const float4*>(g_aggv + n0 * 288);
    const float4* iA1 = reinterpret_cast<const float4*>(g_aggv + n0 * 288 + 96);
    const float4* iA2 = reinterpret_cast<const float4*>(g_aggv + n0 * 288 + 192);
    const float4* iB0 = reinterpret_cast<const float4*>(g_aggv + n1 * 288);
    const float4* iB1 = reinterpret_cast<const float4*>(g_aggv + n1 * 288 + 96);
    const float4* iB2 = reinterpret_cast<const float4*>(g_aggv + n1 * 288 + 192);
#pragma unroll 2
    for (int k4 = 0; k4 < 24; k4++) {
        const float4 a0 = iA0[k4], a1 = iA1[k4], a2 = iA2[k4];
        const float4 b0 = iB0[k4], b1 = iB1[k4], b2 = iB2[k4];
        const float fa0[4] = {a0.x, a0.y, a0.z, a0.w};
        const float fa1[4] = {a1.x, a1.y, a1.z, a1.w};
        const float fa2[4] = {a2.x, a2.y, a2.z, a2.w};
        const float fb0[4] = {b0.x, b0.y, b0.z, b0.w};
        const float fb1[4] = {b1.x, b1.y, b1.z, b1.w};
        const float fb2[4] = {b2.x, b2.y, b2.z, b2.w};
#pragma unroll
        for (int j = 0; j < 4; j++) {
            const float4 w = *reinterpret_cast<const float4*>(sW2v + (k4 * 4 + j) * 32 + ch0);
            accv0[0][0] += fa0[j] * w.x; accv0[0][1] += fa0[j] * w.y;
            accv0[0][2] += fa0[j] * w.z; accv0[0][3] += fa0[j] * w.w;
            accv0[1][0] += fa1[j] * w.x; accv0[1][1] += fa1[j] * w.y;
            accv0[1][2] += fa1[j] * w.z; accv0[1][3] += fa1[j] * w.w;
            accv0[2][0] += fa2[j] * w.x; accv0[2][1] += fa2[j] * w.y;
            accv0[2][2] += fa2[j] * w.z; accv0[2][3] += fa2[j] * w.w;
            accv1[0][0] += fb0[j] * w.x; accv1[0][1] += fb0[j] * w.y;
            accv1[0][2] += fb0[j] * w.z; accv1[0][3] += fb0[j] * w.w;
            accv1[1][0] += fb1[j] * w.x; accv1[1][1] += fb1[j] * w.y;
            accv1[1][2] += fb1[j] * w.z; accv1[1][3] += fb1[j] * w.w;
            accv1[2][0] += fb2[j] * w.x; accv1[2][1] += fb2[j] * w.y;
            accv1[2][2] += fb2[j] * w.z; accv1[2][3] += fb2[j] * w.w;
        }
    }

    // sc_v: M[u, ch-slice] = sum_a attr[a]*Wscv[u,a,ch] per node, applied to 3 comps
    float at0[8], at1[8];
    {
        const float4 a0 = *reinterpret_cast<const float4*>(attrs + n0 * 8);
        const float4 a1 = *reinterpret_cast<const float4*>(attrs + n0 * 8 + 4);
        at0[0]=a0.x; at0[1]=a0.y; at0[2]=a0.z; at0[3]=a0.w;
        at0[4]=a1.x; at0[5]=a1.y; at0[6]=a1.z; at0[7]=a1.w;
        const float4 b0 = *reinterpret_cast<const float4*>(attrs + n1 * 8);
        const float4 b1 = *reinterpret_cast<const float4*>(attrs + n1 * 8 + 4);
        at1[0]=b0.x; at1[1]=b0.y; at1[2]=b0.z; at1[3]=b0.w;
        at1[4]=b1.x; at1[5]=b1.y; at1[6]=b1.z; at1[7]=b1.w;
    }
    const float* nvA = node_v + n0 * 96;
    const float* nvB = node_v + n1 * 96;
#pragma unroll 2
    for (int u = 0; u < 32; u++) {
        float mv0[4] = {0.f, 0.f, 0.f, 0.f};
        float mv1[4] = {0.f, 0.f, 0.f, 0.f};
#pragma unroll
        for (int a = 0; a < 8; a++) {
            const float4 w = *reinterpret_cast<const float4*>(sWscv + (u * 8 + a) * 32 + ch0);
            const float wa0 = at0[a];
            const float wa1 = at1[a];
            mv0[0] += wa0 * w.x; mv0[1] += wa0 * w.y;
            mv0[2] += wa0 * w.z; mv0[3] += wa0 * w.w;
            mv1[0] += wa1 * w.x; mv1[1] += wa1 * w.y;
            mv1[2] += wa1 * w.z; mv1[3] += wa1 * w.w;
        }
        const float va0 = nvA[u * 3 + 0], va1 = nvA[u * 3 + 1], va2 = nvA[u * 3 + 2];
        const float vb0 = nvB[u * 3 + 0], vb1 = nvB[u * 3 + 1], vb2 = nvB[u * 3 + 2];
#pragma unroll
        for (int j = 0; j < 4; j++) {
            accv0[0][j] += va0 * mv0[j];
            accv0[1][j] += va1 * mv0[j];
            accv0[2][j] += va2 * mv0[j];
            accv1[0][j] += vb0 * mv1[j];
            accv1[1][j] += vb1 * mv1[j];
            accv1[2][j] += vb2 * mv1[j];
        }
    }

    // store: out[n*128 + 32 + v*3 + c] for v in [ch0, ch0+4) -> 12 contiguous
    // floats starting at 32 + ch0*3 (16B aligned) -> 3 float4 per node
    {
        float4* o4 = reinterpret_cast<float4*>(out + n0 * 128 + 32 + ch0 * 3);
#pragma unroll
        for (int g = 0; g < 3; g++) {
            const int f0 = g * 4;
            float4 o;
            o.x = accv0[(f0 + 0) % 3][(f0 + 0) / 3];
            o.y = accv0[(f0 + 1) % 3][(f0 + 1) / 3];
            o.z = accv0[(f0 + 2) % 3][(f0 + 2) / 3];
            o.w = accv0[(f0 + 3) % 3][(f0 + 3) / 3];
            o4[g] = o;
        }
    }
    {
        float4* o4 = reinterpret_cast<float4*>(out + n1 * 128 + 32 + ch0 * 3);
#pragma unroll
        for (int g = 0; g < 3; g++) {
            const int f0 = g * 4;
            float4 o;
            o.x = accv1[(f0 + 0) % 3][(f0 + 0) / 3];
            o.y = accv1[(f0 + 1) % 3][(f0 + 1) / 3];
            o.z = accv1[(f0 + 2) % 3][(f0 + 2) / 3];
            o.w = accv1[(f0 + 3) % 3][(f0 + 3) / 3];
            o4[g] = o;
        }
    }
}

// ---------------------------------------------------------------------------
extern "C" void kernel_launch(void* const* d_in, const int* in_sizes, int n_in,
                              void* d_out, int out_size) {
    const float* node_s     = (const float*)d_in[0];
    const float* node_v     = (const float*)d_in[1];
    const float* node_attrs = (const float*)d_in[2];
    const float* edge_emb   = (const float*)d_in[3];
    const float* edge_sh0   = (const float*)d_in[4];
    const float* edge_sh1   = (const float*)d_in[5];
    const float* W1_s       = (const float*)d_in[6];
    const float* W1_v       = (const float*)d_in[7];
    const float* Wm1        = (const float*)d_in[8];
    const float* Wm2        = (const float*)d_in[9];
    const float* W2_s       = (const float*)d_in[10];
    const float* W2_v       = (const float*)d_in[11];
    const float* Wsc_s      = (const float*)d_in[12];
    const float* Wsc_v      = (const float*)d_in[13];
    const int*   edge_src   = (const int*)d_in[14];
    const int*   edge_dst   = (const int*)d_in[15];
    float* out = (float*)d_out;

    // CSR build (by destination)
    zero_cnt_kernel<<<(N_NODES + 255) / 256, 256>>>();
    count_kernel<<<(N_EDGES + 255) / 256, 256>>>(edge_dst);
    scan_kernel<<<1, 1024>>>();
    fill_kernel<<<(N_EDGES + 255) / 256, 256>>>(edge_dst);

    // linear_1 (independent of CSR)
    lin1_kernel<<<(N_NODES + 7) / 8, 256>>>(node_s, node_v, W1_s, W1_v);

    // node-centric edge gather + tensor product (no atomics)
    gather_tp_kernel<<<(N_NODES * 8 + 255) / 256, 256>>>(
        edge_emb, edge_sh0, edge_sh1, edge_src, Wm1, Wm2);

    // linear_2 + self-connection
    node_s_kernel<<<(N_NODES / 2 * 4 + 255) / 256, 256, 10240 * sizeof(float)>>>(
        node_s, node_attrs, W2_s, Wsc_s, out);
    node_v_kernel<<<(N_NODES / 2 * 8 + 255) / 256, 256, 11264 * sizeof(float)>>>(
        node_v, node_attrs, W2_v, Wsc_v, out);
}

// round 9
// speedup vs baseline: 1.0569x; 1.0569x over previous
#include <cuda_runtime.h>
#include <math.h>

#define N_NODES 50000
#define N_EDGES 800000

#define INV_SQRT8  0.35355339059327373f
#define INV_SQRT32 0.17677669529663687f
#define CG_INV3    0.5773502691896258f   // 1/sqrt(3)
#define CG_INV2    0.7071067811865476f   // 1/sqrt(2)
#define MS_SCALE   0.125f                // 1/sqrt(64)
#define MV_SCALE   0.10206207261596575f  // 1/sqrt(96)
#define NSC_SCALE  0.0625f               // 1/sqrt(256)
#define NEIGH_INV  0.25f                 // 1/sqrt(16)

// Scratch (static device memory — no allocation in kernel_launch)
__device__ __align__(16) float g_xs[N_NODES * 32];    // linear_1 scalar out
__device__ __align__(16) float g_xv[N_NODES * 96];    // linear_1 vector out, [N][3][32] comp-major
__device__ __align__(16) float g_aggs[N_NODES * 64];  // aggregated scalars, [N][64]
__device__ __align__(16) float g_aggv[N_NODES * 288]; // aggregated vectors, [N][3][96] comp-major
// CSR-by-destination scratch + CSR-ordered edge payload
__device__ int g_cnt[N_NODES];
__device__ int g_off[N_NODES + 1];
__device__ int g_cur[N_NODES];
__device__ int g_psrc[N_EDGES];
__device__ __align__(16) float  g_pemb[N_EDGES * 8];
__device__ __align__(16) float4 g_psh[N_EDGES];

// ---------------------------------------------------------------------------
// CSR build: zero counts -> count -> scan -> fill(+payload permute)
// ---------------------------------------------------------------------------
__global__ void zero_cnt_kernel() {
    int i = blockIdx.x * blockDim.x + threadIdx.x;
    if (i < N_NODES) g_cnt[i] = 0;
}

__global__ void count_kernel(const int* __restrict__ dst) {
    int e = blockIdx.x * blockDim.x + threadIdx.x;
    if (e < N_EDGES) atomicAdd(&g_cnt[dst[e]], 1);
}

__global__ void scan_kernel() {
    // single block, 1024 threads; chunked exclusive prefix sum over 50000
    __shared__ int part[1024];
    const int CH = (N_NODES + 1023) / 1024;   // 49
    const int t = threadIdx.x;
    const int lo = t * CH;
    const int hi = min(lo + CH, N_NODES);
    int s = 0;
    for (int i = lo; i < hi; i++) s += g_cnt[i];
    part[t] = s;
    __syncthreads();
    if (t == 0) {
        int run = 0;
        for (int i = 0; i < 1024; i++) { int tmp = part[i]; part[i] = run; run += tmp; }
    }
    __syncthreads();
    int run = part[t];
    for (int i = lo; i < hi; i++) {
        g_off[i] = run;
        g_cur[i] = run;
        run += g_cnt[i];
    }
    if (t == 0) g_off[N_NODES] = N_EDGES;
}

// fill: claim CSR slot and materialize the permuted edge payload there.
// Reads fully coalesced (e-order); writes scattered (p-order) but write-only.
__global__ void fill_kernel(const int* __restrict__ dst,
                            const int* __restrict__ src,
                            const float* __restrict__ emb,
                            const float* __restrict__ sh0,
                            const float* __restrict__ sh1) {
    int e = blockIdx.x * blockDim.x + threadIdx.x;
    if (e >= N_EDGES) return;
    int p = atomicAdd(&g_cur[dst[e]], 1);
    g_psrc[p] = src[e];
    const float4* er = reinterpret_cast<const float4*>(emb + e * 8);
    float4* pw = reinterpret_cast<float4*>(g_pemb + p * 8);
    pw[0] = er[0];
    pw[1] = er[1];
    g_psh[p] = make_float4(sh0[e], sh1[e * 3 + 0], sh1[e * 3 + 1], sh1[e * 3 + 2]);
}

// ---------------------------------------------------------------------------
// linear_1 (per-l equivariant channel mixing), one warp per node
// ---------------------------------------------------------------------------
__global__ void lin1_kernel(const float* __restrict__ node_s,
                            const float* __restrict__ node_v,
                            const float* __restrict__ W1s,
                            const float* __restrict__ W1v) {
    __shared__ float sW1s[1024];
    __shared__ float sW1v[1024];
    for (int i = threadIdx.x; i < 1024; i += blockDim.x) {
        sW1s[i] = W1s[i];
        sW1v[i] = W1v[i];
    }
    __syncthreads();

    const int warp = (blockIdx.x * blockDim.x + threadIdx.x) >> 5;
    const int lane = threadIdx.x & 31;
    if (warp >= N_NODES) return;
    const int n = warp;

    float sl = node_s[n * 32 + lane];
    float acc = 0.f;
#pragma unroll
    for (int u = 0; u < 32; u++)
        acc += __shfl_sync(0xffffffffu, sl, u) * sW1s[u * 32 + lane];
    g_xs[n * 32 + lane] = acc * INV_SQRT32;

#pragma unroll
    for (int c = 0; c < 3; c++) {
        float vl = node_v[n * 96 + lane * 3 + c];
        float a = 0.f;
#pragma unroll
        for (int u = 0; u < 32; u++)
            a += __shfl_sync(0xffffffffu, vl, u) * sW1v[u * 32 + lane];
        g_xv[n * 96 + c * 32 + lane] = a * INV_SQRT32;
    }
}

// ---------------------------------------------------------------------------
// Node-centric gather + radial MLP + CG tensor product. NO ATOMICS.
// 8 threads per node; thread `sub` owns channels [4*sub, 4*sub+3].
// Edge payload is CSR-permuted -> all streaming reads are sequential.
// ---------------------------------------------------------------------------
__global__ __launch_bounds__(256) void gather_tp_kernel(const int* __restrict__ dummy) {
    __shared__ float sWm1[64];
    __shared__ float sWm2[1280];
    const float wscale = INV_SQRT8 * NEIGH_INV;   // fold 1/sqrt(HID), 1/sqrt(avg_neigh)
    {
        // weights staged from __device__ globals' twins: we pass them in smem
    }
    // NOTE: weights loaded by host-pointer args below
    (void)dummy;
    // (actual staging happens in gather_tp_body via template-free args)
    // -- this kernel body is replaced below --
}

__global__ __launch_bounds__(256) void gather_tp(
        const float* __restrict__ Wm1,
        const float* __restrict__ Wm2) {
    __shared__ float sWm1[64];
    __shared__ float sWm2[1280];
    const float wscale = INV_SQRT8 * NEIGH_INV;   // fold 1/sqrt(HID), 1/sqrt(avg_neigh)
    for (int i = threadIdx.x; i < 64; i += blockDim.x) sWm1[i] = Wm1[i];
    for (int i = threadIdx.x; i < 1280; i += blockDim.x) sWm2[i] = Wm2[i] * wscale;
    __syncthreads();

    const int gt = blockIdx.x * blockDim.x + threadIdx.x;
    const int n = gt >> 3;
    if (n >= N_NODES) return;
    const int sub = gt & 7;
    const int u0 = sub * 4;
    const unsigned lane = threadIdx.x & 31u;
    const unsigned gmask = 0xFFu << (lane & 24u);   // this thread's 8-lane group

    // per-thread Wm1 column in registers
    float wm1r[8];
#pragma unroll
    for (int k = 0; k < 8; k++) wm1r[k] = sWm1[k * 8 + sub];

    const int beg = g_off[n];
    const int end = g_off[n + 1];

    float aP1[4], aP2[4], aP3[3][4], aP4[3][4], aP5[3][4];
#pragma unroll
    for (int j = 0; j < 4; j++) { aP1[j] = 0.f; aP2[j] = 0.f; }
#pragma unroll
    for (int c = 0; c < 3; c++)
#pragma unroll
        for (int j = 0; j < 4; j++) { aP3[c][j] = 0.f; aP4[c][j] = 0.f; aP5[c][j] = 0.f; }

    for (int i = beg; i < end; i++) {
        // ---- streaming, CSR-ordered payload ----
        const float embv = __ldg(&g_pemb[i * 8 + sub]);   // 8 lanes consecutive
        const float4 sh  = __ldg(&g_psh[i]);              // broadcast in group
        const int ns     = __ldg(&g_psrc[i]);             // broadcast in group
        const float q0 = sh.x, s1x = sh.y, s1y = sh.z, s1z = sh.w;

        // ---- radial MLP (8-wide across the group) ----
        float hacc = 0.f;
#pragma unroll
        for (int k = 0; k < 8; k++)
            hacc += __shfl_sync(gmask, embv, k, 8) * wm1r[k];
        hacc *= INV_SQRT8;
        const float h = hacc / (1.f + expf(-hacc));   // silu

        float w[5][4];
#pragma unroll
        for (int p = 0; p < 5; p++)
#pragma unroll
            for (int j = 0; j < 4; j++) w[p][j] = 0.f;
#pragma unroll
        for (int k = 0; k < 8; k++) {
            const float hk = __shfl_sync(gmask, h, k, 8);
            const float* wrow = &sWm2[k * 160 + u0];
#pragma unroll
            for (int p = 0; p < 5; p++)
#pragma unroll
                for (int j = 0; j < 4; j++)
                    w[p][j] += hk * wrow[p * 32 + j];
        }

        // ---- gather source features (L2-resident scratch) ----
        const float4 S  = *reinterpret_cast<const float4*>(g_xs + ns * 32 + u0);
        const float4 VX = *reinterpret_cast<const float4*>(g_xv + ns * 96 + u0);
        const float4 VY = *reinterpret_cast<const float4*>(g_xv + ns * 96 + 32 + u0);
        const float4 VZ = *reinterpret_cast<const float4*>(g_xv + ns * 96 + 64 + u0);
        const float s_[4] = {S.x, S.y, S.z, S.w};
        const float vx[4] = {VX.x, VX.y, VX.z, VX.w};
        const float vy[4] = {VY.x, VY.y, VY.z, VY.w};
        const float vz[4] = {VZ.x, VZ.y, VZ.z, VZ.w};

#pragma unroll
        for (int j = 0; j < 4; j++) {
            const float dot = vx[j] * s1x + vy[j] * s1y + vz[j] * s1z;
            const float cx = vy[j] * s1z - vz[j] * s1y;
            const float cy = vz[j] * s1x - vx[j] * s1z;
            const float cz = vx[j] * s1y - vy[j] * s1x;
            aP1[j] += w[0][j] * s_[j] * q0;
            aP2[j] += w[1][j] * dot * CG_INV3;
            const float t3 = w[2][j] * s_[j];
            aP3[0][j] += t3 * s1x;
            aP3[1][j] += t3 * s1y;
            aP3[2][j] += t3 * s1z;
            const float t4 = w[3][j] * q0;
            aP4[0][j] += t4 * vx[j];
            aP4[1][j] += t4 * vy[j];
            aP4[2][j] += t4 * vz[j];
            const float t5 = w[4][j] * CG_INV2;
            aP5[0][j] += t5 * cx;
            aP5[1][j] += t5 * cy;
            aP5[2][j] += t5 * cz;
        }
    }

    // ---- plain stores (every element written; no zero-init pass needed) ----
    float* as_base = g_aggs + n * 64 + u0;
    *reinterpret_cast<float4*>(as_base)      = make_float4(aP1[0], aP1[1], aP1[2], aP1[3]);
    *reinterpret_cast<float4*>(as_base + 32) = make_float4(aP2[0], aP2[1], aP2[2], aP2[3]);
#pragma unroll
    for (int c = 0; c < 3; c++) {
        float* av_base = g_aggv + n * 288 + c * 96 + u0;
        *reinterpret_cast<float4*>(av_base)      = make_float4(aP3[c][0], aP3[c][1], aP3[c][2], aP3[c][3]);
        *reinterpret_cast<float4*>(av_base + 32) = make_float4(aP4[c][0], aP4[c][1], aP4[c][2], aP4[c][3]);
        *reinterpret_cast<float4*>(av_base + 64) = make_float4(aP5[c][0], aP5[c][1], aP5[c][2], aP5[c][3]);
    }
}

// ---------------------------------------------------------------------------
// Scalar output: agg_s @ W2s + scalar self-connection.
// 2 NODES x 8 CHANNELS per thread: each weight LDS.128 feeds 2x the FFMA.
// ---------------------------------------------------------------------------
__global__ __launch_bounds__(256) void node_s_kernel(
        const float* __restrict__ node_s,
        const float* __restrict__ attrs,
        const float* __restrict__ W2s,
        const float* __restrict__ Wscs,
        float* __restrict__ out) {
    extern __shared__ float sw[];
    float* sW2s  = sw;          // 2048 floats
    float* sWscs = sw + 2048;   // 8192 floats
    for (int i = threadIdx.x; i < 2048; i += blockDim.x)
        sW2s[i] = W2s[i] * MS_SCALE;
    for (int i = threadIdx.x; i < 8192; i += blockDim.x)
        sWscs[i] = Wscs[i] * NSC_SCALE;
    __syncthreads();

    const int gt = blockIdx.x * blockDim.x + threadIdx.x;
    const int pair = gt >> 2;
    if (pair >= N_NODES / 2) return;
    const int ch0 = (gt & 3) * 8;
    const int n0 = pair * 2;
    const int n1 = n0 + 1;

    float acc0[8], acc1[8];
#pragma unroll
    for (int j = 0; j < 8; j++) { acc0[j] = 0.f; acc1[j] = 0.f; }

    // m_s for both nodes
    const float4* inA = reinterpret_cast<const float4*>(g_aggs + n0 * 64);
    const float4* inB = reinterpret_cast<const float4*>(g_aggs + n1 * 64);
#pragma unroll 4
    for (int k4 = 0; k4 < 16; k4++) {
        const float4 av = inA[k4];
        const float4 bv = inB[k4];
        const float a[4] = {av.x, av.y, av.z, av.w};
        const float b[4] = {bv.x, bv.y, bv.z, bv.w};
#pragma unroll
        for (int j = 0; j < 4; j++) {
            const float4* wr = reinterpret_cast<const float4*>(sW2s + (k4 * 4 + j) * 32 + ch0);
            const float4 w0 = wr[0];
            const float4 w1 = wr[1];
            acc0[0] += a[j] * w0.x; acc0[1] += a[j] * w0.y;
            acc0[2] += a[j] * w0.z; acc0[3] += a[j] * w0.w;
            acc0[4] += a[j] * w1.x; acc0[5] += a[j] * w1.y;
            acc0[6] += a[j] * w1.z; acc0[7] += a[j] * w1.w;
            acc1[0] += b[j] * w0.x; acc1[1] += b[j] * w0.y;
            acc1[2] += b[j] * w0.z; acc1[3] += b[j] * w0.w;
            acc1[4] += b[j] * w1.x; acc1[5] += b[j] * w1.y;
            acc1[6] += b[j] * w1.z; acc1[7] += b[j] * w1.w;
        }
    }

    // sc_s for both nodes
    float at0[8], at1[8];
    {
        const float4 a0 = *reinterpret_cast<const float4*>(attrs + n0 * 8);
        const float4 a1 = *reinterpret_cast<const float4*>(attrs + n0 * 8 + 4);
        at0[0]=a0.x; at0[1]=a0.y; at0[2]=a0.z; at0[3]=a0.w;
        at0[4]=a1.x; at0[5]=a1.y; at0[6]=a1.z; at0[7]=a1.w;
        const float4 b0 = *reinterpret_cast<const float4*>(attrs + n1 * 8);
        const float4 b1 = *reinterpret_cast<const float4*>(attrs + n1 * 8 + 4);
        at1[0]=b0.x; at1[1]=b0.y; at1[2]=b0.z; at1[3]=b0.w;
        at1[4]=b1.x; at1[5]=b1.y; at1[6]=b1.z; at1[7]=b1.w;
    }
    const float4* nsA = reinterpret_cast<const float4*>(node_s + n0 * 32);
    const float4* nsB = reinterpret_cast<const float4*>(node_s + n1 * 32);
#pragma unroll 2
    for (int u4 = 0; u4 < 8; u4++) {
        const float4 sa = nsA[u4];
        const float4 sb = nsB[u4];
        const float sua[4] = {sa.x, sa.y, sa.z, sa.w};
        const float sub_[4] = {sb.x, sb.y, sb.z, sb.w};
#pragma unroll
        for (int j = 0; j < 4; j++) {
            const int u = u4 * 4 + j;
#pragma unroll
            for (int a = 0; a < 8; a++) {
                const float za = sua[j] * at0[a];
                const float zb = sub_[j] * at1[a];
                const float4* wr = reinterpret_cast<const float4*>(sWscs + (u * 8 + a) * 32 + ch0);
                const float4 w0 = wr[0];
                const float4 w1 = wr[1];
                acc0[0] += za * w0.x; acc0[1] += za * w0.y;
                acc0[2] += za * w0.z; acc0[3] += za * w0.w;
                acc0[4] += za * w1.x; acc0[5] += za * w1.y;
                acc0[6] += za * w1.z; acc0[7] += za * w1.w;
                acc1[0] += zb * w0.x; acc1[1] += zb * w0.y;
                acc1[2] += zb * w0.z; acc1[3] += zb * w0.w;
                acc1[4] += zb * w1.x; acc1[5] += zb * w1.y;
                acc1[6] += zb * w1.z; acc1[7] += zb * w1.w;
            }
        }
    }

    float4* o0 = reinterpret_cast<float4*>(out + n0 * 128 + ch0);
    o0[0] = make_float4(acc0[0], acc0[1], acc0[2], acc0[3]);
    o0[1] = make_float4(acc0[4], acc0[5], acc0[6], acc0[7]);
    float4* o1 = reinterpret_cast<float4*>(out + n1 * 128 + ch0);
    o1[0] = make_float4(acc1[0], acc1[1], acc1[2], acc1[3]);
    o1[1] = make_float4(acc1[4], acc1[5], acc1[6], acc1[7]);
}

// ---------------------------------------------------------------------------
// Vector output: agg_v @ W2v + vector self-connection.
// 2 NODES x 4 CHANNELS per thread; weight LDS.128 reused across 3 comps x 2 nodes.
// ---------------------------------------------------------------------------
__global__ __launch_bounds__(256) void node_v_kernel(
        const float* __restrict__ node_v,
        const float* __restrict__ attrs,
        const float* __restrict__ W2v,
        const float* __restrict__ Wscv,
        float* __restrict__ out) {
    extern __shared__ float sw[];
    float* sW2v  = sw;          // 3072 floats
    float* sWscv = sw + 3072;   // 8192 floats
    for (int i = threadIdx.x; i < 3072; i += blockDim.x)
        sW2v[i] = W2v[i] * MV_SCALE;
    for (int i = threadIdx.x; i < 8192; i += blockDim.x)
        sWscv[i] = Wscv[i] * NSC_SCALE;
    __syncthreads();

    const int gt = blockIdx.x * blockDim.x + threadIdx.x;
    const int pair = gt >> 3;
    if (pair >= N_NODES / 2) return;
    const int ch0 = (gt & 7) * 4;
    const int n0 = pair * 2;
    const int n1 = n0 + 1;

    float accv0[3][4], accv1[3][4];
#pragma unroll
    for (int c = 0; c < 3; c++)
#pragma unroll
        for (int j = 0; j < 4; j++) { accv0[c][j] = 0.f; accv1[c][j] = 0.f; }

    const float4* iA0 = reinterpret_cast<const float4*>(g_aggv + n0 * 288);
    const float4* iA1 = reinterpret_cast<const float4*>(g_aggv + n0 * 288 + 96);
    const float4* iA2 = reinterpret_cast<const float4*>(g_aggv + n0 * 288 + 192);
    const float4* iB0 = reinterpret_cast<const float4*>(g_aggv + n1 * 288);
    const float4* iB1 = reinterpret_cast<const float4*>(g_aggv + n1 * 288 + 96);
    const float4* iB2 = reinterpret_cast<const float4*>(g_aggv + n1 * 288 + 192);
#pragma unroll 2
    for (int k4 = 0; k4 < 24; k4++) {
        const float4 a0 = iA0[k4], a1 = iA1[k4], a2 = iA2[k4];
        const float4 b0 = iB0[k4], b1 = iB1[k4], b2 = iB2[k4];
        const float fa0[4] = {a0.x, a0.y, a0.z, a0.w};
        const float fa1[4] = {a1.x, a1.y, a1.z, a1.w};
        const float fa2[4] = {a2.x, a2.y, a2.z, a2.w};
        const float fb0[4] = {b0.x, b0.y, b0.z, b0.w};
        const float fb1[4] = {b1.x, b1.y, b1.z, b1.w};
        const float fb2[4] = {b2.x, b2.y, b2.z, b2.w};
#pragma unroll
        for (int j = 0; j < 4; j++) {
            const float4 w = *reinterpret_cast<const float4*>(sW2v + (k4 * 4 + j) * 32 + ch0);
            accv0[0][0] += fa0[j] * w.x; accv0[0][1] += fa0[j] * w.y;
            accv0[0][2] += fa0[j] * w.z; accv0[0][3] += fa0[j] * w.w;
            accv0[1][0] += fa1[j] * w.x; accv0[1][1] += fa1[j] * w.y;
            accv0[1][2] += fa1[j] * w.z; accv0[1][3] += fa1[j] * w.w;
            accv0[2][0] += fa2[j] * w.x; accv0[2][1] += fa2[j] * w.y;
            accv0[2][2] += fa2[j] * w.z; accv0[2][3] += fa2[j] * w.w;
            accv1[0][0] += fb0[j] * w.x; accv1[0][1] += fb0[j] * w.y;
            accv1[0][2] += fb0[j] * w.z; accv1[0][3] += fb0[j] * w.w;
            accv1[1][0] += fb1[j] * w.x; accv1[1][1] += fb1[j] * w.y;
            accv1[1][2] += fb1[j] * w.z; accv1[1][3] += fb1[j] * w.w;
            accv1[2][0] += fb2[j] * w.x; accv1[2][1] += fb2[j] * w.y;
            accv1[2][2] += fb2[j] * w.z; accv1[2][3] += fb2[j] * w.w;
        }
    }

    float at0[8], at1[8];
    {
        const float4 a0 = *reinterpret_cast<const float4*>(attrs + n0 * 8);
        const float4 a1 = *reinterpret_cast<const float4*>(attrs + n0 * 8 + 4);
        at0[0]=a0.x; at0[1]=a0.y; at0[2]=a0.z; at0[3]=a0.w;
        at0[4]=a1.x; at0[5]=a1.y; at0[6]=a1.z; at0[7]=a1.w;
        const float4 b0 = *reinterpret_cast<const float4*>(attrs + n1 * 8);
        const float4 b1 = *reinterpret_cast<const float4*>(attrs + n1 * 8 + 4);
        at1[0]=b0.x; at1[1]=b0.y; at1[2]=b0.z; at1[3]=b0.w;
        at1[4]=b1.x; at1[5]=b1.y; at1[6]=b1.z; at1[7]=b1.w;
    }
    const float* nvA = node_v + n0 * 96;
    const float* nvB = node_v + n1 * 96;
#pragma unroll 2
    for (int u = 0; u < 32; u++) {
        float mv0[4] = {0.f, 0.f, 0.f, 0.f};
        float mv1[4] = {0.f, 0.f, 0.f, 0.f};
#pragma unroll
        for (int a = 0; a < 8; a++) {
            const float4 w = *reinterpret_cast<const float4*>(sWscv + (u * 8 + a) * 32 + ch0);
            const float wa0 = at0[a];
            const float wa1 = at1[a];
            mv0[0] += wa0 * w.x; mv0[1] += wa0 * w.y;
            mv0[2] += wa0 * w.z; mv0[3] += wa0 * w.w;
            mv1[0] += wa1 * w.x; mv1[1] += wa1 * w.y;
            mv1[2] += wa1 * w.z; mv1[3] += wa1 * w.w;
        }
        const float va0 = nvA[u * 3 + 0], va1 = nvA[u * 3 + 1], va2 = nvA[u * 3 + 2];
        const float vb0 = nvB[u * 3 + 0], vb1 = nvB[u * 3 + 1], vb2 = nvB[u * 3 + 2];
#pragma unroll
        for (int j = 0; j < 4; j++) {
            accv0[0][j] += va0 * mv0[j];
            accv0[1][j] += va1 * mv0[j];
            accv0[2][j] += va2 * mv0[j];
            accv1[0][j] += vb0 * mv1[j];
            accv1[1][j] += vb1 * mv1[j];
            accv1[2][j] += vb2 * mv1[j];
        }
    }

    {
        float4* o4 = reinterpret_cast<float4*>(out + n0 * 128 + 32 + ch0 * 3);
#pragma unroll
        for (int g = 0; g < 3; g++) {
            const int f0 = g * 4;
            float4 o;
            o.x = accv0[(f0 + 0) % 3][(f0 + 0) / 3];
            o.y = accv0[(f0 + 1) % 3][(f0 + 1) / 3];
            o.z = accv0[(f0 + 2) % 3][(f0 + 2) / 3];
            o.w = accv0[(f0 + 3) % 3][(f0 + 3) / 3];
            o4[g] = o;
        }
    }
    {
        float4* o4 = reinterpret_cast<float4*>(out + n1 * 128 + 32 + ch0 * 3);
#pragma unroll
        for (int g = 0; g < 3; g++) {
            const int f0 = g * 4;
            float4 o;
            o.x = accv1[(f0 + 0) % 3][(f0 + 0) / 3];
            o.y = accv1[(f0 + 1) % 3][(f0 + 1) / 3];
            o.z = accv1[(f0 + 2) % 3][(f0 + 2) / 3];
            o.w = accv1[(f0 + 3) % 3][(f0 + 3) / 3];
            o4[g] = o;
        }
    }
}

// ---------------------------------------------------------------------------
extern "C" void kernel_launch(void* const* d_in, const int* in_sizes, int n_in,
                              void* d_out, int out_size) {
    const float* node_s     = (const float*)d_in[0];
    const float* node_v     = (const float*)d_in[1];
    const float* node_attrs = (const float*)d_in[2];
    const float* edge_emb   = (const float*)d_in[3];
    const float* edge_sh0   = (const float*)d_in[4];
    const float* edge_sh1   = (const float*)d_in[5];
    const float* W1_s       = (const float*)d_in[6];
    const float* W1_v       = (const float*)d_in[7];
    const float* Wm1        = (const float*)d_in[8];
    const float* Wm2        = (const float*)d_in[9];
    const float* W2_s       = (const float*)d_in[10];
    const float* W2_v       = (const float*)d_in[11];
    const float* Wsc_s      = (const float*)d_in[12];
    const float* Wsc_v      = (const float*)d_in[13];
    const int*   edge_src   = (const int*)d_in[14];
    const int*   edge_dst   = (const int*)d_in[15];
    float* out = (float*)d_out;

    // CSR build + payload permutation (by destination)
    zero_cnt_kernel<<<(N_NODES + 255) / 256, 256>>>();
    count_kernel<<<(N_EDGES + 255) / 256, 256>>>(edge_dst);
    scan_kernel<<<1, 1024>>>();
    fill_kernel<<<(N_EDGES + 255) / 256, 256>>>(edge_dst, edge_src,
                                                edge_emb, edge_sh0, edge_sh1);

    // linear_1 (independent of CSR)
    lin1_kernel<<<(N_NODES + 7) / 8, 256>>>(node_s, node_v, W1_s, W1_v);

    // node-centric edge gather + tensor product (no atomics, streaming reads)
    gather_tp<<<(N_NODES * 8 + 255) / 256, 256>>>(Wm1, Wm2);

    // linear_2 + self-connection
    node_s_kernel<<<(N_NODES / 2 * 4 + 255) / 256, 256, 10240 * sizeof(float)>>>(
        node_s, node_attrs, W2_s, Wsc_s, out);
    node_v_kernel<<<(N_NODES / 2 * 8 + 255) / 256, 256, 11264 * sizeof(float)>>>(
        node_v, node_attrs, W2_v, Wsc_v, out);
}

// round 10
// speedup vs baseline: 1.0744x; 1.0166x over previous
#include <cuda_runtime.h>
#include <math.h>

#define N_NODES 50000
#define N_EDGES 800000

#define INV_SQRT8  0.35355339059327373f
#define INV_SQRT32 0.17677669529663687f
#define CG_INV3    0.5773502691896258f   // 1/sqrt(3)
#define CG_INV2    0.7071067811865476f   // 1/sqrt(2)
#define MS_SCALE   0.125f                // 1/sqrt(64)
#define MV_SCALE   0.10206207261596575f  // 1/sqrt(96)
#define NSC_SCALE  0.0625f               // 1/sqrt(256)
#define NEIGH_INV  0.25f                 // 1/sqrt(16)

typedef unsigned long long u64;

// Scratch (static device memory — no allocation in kernel_launch)
__device__ __align__(16) float g_xs[N_NODES * 32];    // linear_1 scalar out
__device__ __align__(16) float g_xv[N_NODES * 96];    // linear_1 vector out, [N][3][32] comp-major
__device__ __align__(16) float g_aggs[N_NODES * 64];  // aggregated scalars, [N][64]
__device__ __align__(16) float g_aggv[N_NODES * 288]; // aggregated vectors, [N][3][96] comp-major
// CSR-by-destination scratch + CSR-ordered edge payload
__device__ int g_cnt[N_NODES];
__device__ int g_off[N_NODES + 1];
__device__ int g_cur[N_NODES];
__device__ int g_psrc[N_EDGES];
__device__ __align__(16) float  g_pemb[N_EDGES * 8];
__device__ __align__(16) float4 g_psh[N_EDGES];

// ---- f32x2 packed helpers (sm_103a SIMD fp32 pairs) ----
__device__ __forceinline__ u64 pk2(float x) {
    u64 r;
    asm("mov.b64 %0, {%1, %1};" : "=l"(r) : "f"(x));
    return r;
}
__device__ __forceinline__ void fma2(u64& d, u64 a, u64 b) {          // d = a*b + d
    asm("fma.rn.f32x2 %0, %1, %2, %0;" : "+l"(d) : "l"(a), "l"(b));
}
__device__ __forceinline__ u64 fma2r(u64 a, u64 b, u64 c) {           // a*b + c
    u64 r;
    asm("fma.rn.f32x2 %0, %1, %2, %3;" : "=l"(r) : "l"(a), "l"(b), "l"(c));
    return r;
}
__device__ __forceinline__ u64 mul2(u64 a, u64 b) {
    u64 r;
    asm("mul.rn.f32x2 %0, %1, %2;" : "=l"(r) : "l"(a), "l"(b));
    return r;
}
__device__ __forceinline__ u64 add2(u64 a, u64 b) {
    u64 r;
    asm("add.rn.f32x2 %0, %1, %2;" : "=l"(r) : "l"(a), "l"(b));
    return r;
}

// ---------------------------------------------------------------------------
// CSR build: zero counts -> count -> scan -> fill(+payload permute)
// ---------------------------------------------------------------------------
__global__ void zero_cnt_kernel() {
    int i = blockIdx.x * blockDim.x + threadIdx.x;
    if (i < N_NODES) g_cnt[i] = 0;
}

__global__ void count_kernel(const int* __restrict__ dst) {
    int e = blockIdx.x * blockDim.x + threadIdx.x;
    if (e < N_EDGES) atomicAdd(&g_cnt[dst[e]], 1);
}

// hierarchical shuffle scan (no serial thread-0 loop)
__global__ void scan_kernel() {
    __shared__ int wsum[32];
    const int CH = (N_NODES + 1023) / 1024;   // 49
    const int t = threadIdx.x;
    const int lo = t * CH;
    const int hi = min(lo + CH, N_NODES);
    int s = 0;
    for (int i = lo; i < hi; i++) s += g_cnt[i];

    const int lane = t & 31, wid = t >> 5;
    int v = s;
#pragma unroll
    for (int d = 1; d < 32; d <<= 1) {
        int o = __shfl_up_sync(0xffffffffu, v, d);
        if (lane >= d) v += o;
    }
    if (lane == 31) wsum[wid] = v;
    __syncthreads();
    if (wid == 0) {
        int w = wsum[lane];
#pragma unroll
        for (int d = 1; d < 32; d <<= 1) {
            int o = __shfl_up_sync(0xffffffffu, w, d);
            if (lane >= d) w += o;
        }
        wsum[lane] = w;
    }
    __syncthreads();
    int run = v - s + (wid ? wsum[wid - 1] : 0);   // exclusive prefix for this thread
    for (int i = lo; i < hi; i++) {
        g_off[i] = run;
        g_cur[i] = run;
        run += g_cnt[i];
    }
    if (t == 0) g_off[N_NODES] = N_EDGES;
}

// fill: claim CSR slot and materialize the permuted edge payload there.
__global__ void fill_kernel(const int* __restrict__ dst,
                            const int* __restrict__ src,
                            const float* __restrict__ emb,
                            const float* __restrict__ sh0,
                            const float* __restrict__ sh1) {
    int e = blockIdx.x * blockDim.x + threadIdx.x;
    if (e >= N_EDGES) return;
    int p = atomicAdd(&g_cur[dst[e]], 1);
    g_psrc[p] = src[e];
    const float4* er = reinterpret_cast<const float4*>(emb + e * 8);
    float4* pw = reinterpret_cast<float4*>(g_pemb + p * 8);
    pw[0] = er[0];
    pw[1] = er[1];
    g_psh[p] = make_float4(sh0[e], sh1[e * 3 + 0], sh1[e * 3 + 1], sh1[e * 3 + 2]);
}

// ---------------------------------------------------------------------------
// linear_1 (per-l equivariant channel mixing), one warp per node
// ---------------------------------------------------------------------------
__global__ void lin1_kernel(const float* __restrict__ node_s,
                            const float* __restrict__ node_v,
                            const float* __restrict__ W1s,
                            const float* __restrict__ W1v) {
    __shared__ float sW1s[1024];
    __shared__ float sW1v[1024];
    for (int i = threadIdx.x; i < 1024; i += blockDim.x) {
        sW1s[i] = W1s[i];
        sW1v[i] = W1v[i];
    }
    __syncthreads();

    const int warp = (blockIdx.x * blockDim.x + threadIdx.x) >> 5;
    const int lane = threadIdx.x & 31;
    if (warp >= N_NODES) return;
    const int n = warp;

    float sl = node_s[n * 32 + lane];
    float acc = 0.f;
#pragma unroll
    for (int u = 0; u < 32; u++)
        acc += __shfl_sync(0xffffffffu, sl, u) * sW1s[u * 32 + lane];
    g_xs[n * 32 + lane] = acc * INV_SQRT32;

#pragma unroll
    for (int c = 0; c < 3; c++) {
        float vl = node_v[n * 96 + lane * 3 + c];
        float a = 0.f;
#pragma unroll
        for (int u = 0; u < 32; u++)
            a += __shfl_sync(0xffffffffu, vl, u) * sW1v[u * 32 + lane];
        g_xv[n * 96 + c * 32 + lane] = a * INV_SQRT32;
    }
}

// ---------------------------------------------------------------------------
// gather_tp: WARP PER NODE, f32x2-packed math, no atomics.
// lane = es*8 + sub: 4 edge-slots process 4 consecutive CSR edges per
// iteration; sub owns channel pairs (u0..u0+3 packed as two f32x2).
// Butterfly reduce across edge-slots at the end.
// CG_INV3 folded into Wm2 path 1, CG_INV2 into path 4 at staging time.
// ---------------------------------------------------------------------------
__global__ __launch_bounds__(256) void gather_tp(
        const float* __restrict__ Wm1,
        const float* __restrict__ Wm2) {
    __shared__ float sWm1[64];
    __shared__ __align__(16) float sWm2[1280];
    for (int i = threadIdx.x; i < 64; i += blockDim.x) sWm1[i] = Wm1[i];
    for (int i = threadIdx.x; i < 1280; i += blockDim.x) {
        const int p = (i % 160) >> 5;
        float sc = INV_SQRT8 * NEIGH_INV;
        if (p == 1) sc *= CG_INV3;
        if (p == 4) sc *= CG_INV2;
        sWm2[i] = Wm2[i] * sc;
    }
    __syncthreads();

    const int warp = (blockIdx.x * blockDim.x + threadIdx.x) >> 5;
    if (warp >= N_NODES) return;
    const int n = warp;
    const int lane = threadIdx.x & 31;
    const int es  = lane >> 3;       // edge slot 0..3
    const int sub = lane & 7;        // channel group 0..7
    const int u0 = sub * 4;
    const unsigned gmask = 0xFFu << (es * 8);

    float wm1r[8];
#pragma unroll
    for (int k = 0; k < 8; k++) wm1r[k] = sWm1[k * 8 + sub];

    const int beg = g_off[n];
    const int end = g_off[n + 1];

    // packed accumulators: a = channels (u0,u0+1), b = (u0+2,u0+3)
    u64 A1a = 0, A1b = 0, A2a = 0, A2b = 0;
    u64 A3a[3] = {0, 0, 0}, A3b[3] = {0, 0, 0};
    u64 A4a[3] = {0, 0, 0}, A4b[3] = {0, 0, 0};
    u64 A5a[3] = {0, 0, 0}, A5b[3] = {0, 0, 0};

    for (int i = beg + es; i < end; i += 4) {
        const float embv = g_pemb[i * 8 + sub];
        const float4 sh  = g_psh[i];
        const int ns     = g_psrc[i];
        const float s1x = sh.y, s1y = sh.z, s1z = sh.w;

        // ---- radial MLP layer 1 + silu ----
        float hacc = 0.f;
#pragma unroll
        for (int k = 0; k < 8; k++)
            hacc += __shfl_sync(gmask, embv, k, 8) * wm1r[k];
        hacc *= INV_SQRT8;
        const float h = __fdividef(hacc, 1.f + __expf(-hacc));

        // ---- layer 2 matvec, packed: w[p] pairs ----
        u64 w01[5] = {0, 0, 0, 0, 0};
        u64 w23[5] = {0, 0, 0, 0, 0};
#pragma unroll
        for (int k = 0; k < 8; k++) {
            const u64 hk2 = pk2(__shfl_sync(gmask, h, k, 8));
            const ulonglong2* wr = reinterpret_cast<const ulonglong2*>(sWm2 + k * 160 + u0);
#pragma unroll
            for (int p = 0; p < 5; p++) {
                const ulonglong2 wv = wr[p * 8];   // p*32 floats ahead
                fma2(w01[p], hk2, wv.x);
                fma2(w23[p], hk2, wv.y);
            }
        }

        // ---- source features (packed pairs) ----
        const ulonglong2 S2  = *reinterpret_cast<const ulonglong2*>(g_xs + ns * 32 + u0);
        const ulonglong2 VX2 = *reinterpret_cast<const ulonglong2*>(g_xv + ns * 96 + u0);
        const ulonglong2 VY2 = *reinterpret_cast<const ulonglong2*>(g_xv + ns * 96 + 32 + u0);
        const ulonglong2 VZ2 = *reinterpret_cast<const ulonglong2*>(g_xv + ns * 96 + 64 + u0);

        const u64 q02 = pk2(sh.x);
        const u64 x2  = pk2(s1x), y2 = pk2(s1y), z2 = pk2(s1z);
        const u64 nx2 = pk2(-s1x), ny2 = pk2(-s1y), nz2 = pk2(-s1z);

        // pair a (channels u0, u0+1)
        {
            const u64 vx = VX2.x, vy = VY2.x, vz = VZ2.x, ss = S2.x;
            const u64 dot = fma2r(vx, x2, fma2r(vy, y2, mul2(vz, z2)));
            const u64 cx = fma2r(vz, ny2, mul2(vy, z2));   // vy*s1z - vz*s1y
            const u64 cy = fma2r(vx, nz2, mul2(vz, x2));   // vz*s1x - vx*s1z
            const u64 cz = fma2r(vy, nx2, mul2(vx, y2));   // vx*s1y - vy*s1x
            const u64 t1 = mul2(w01[0], ss);
            fma2(A1a, t1, q02);
            fma2(A2a, w01[1], dot);
            const u64 t3 = mul2(w01[2], ss);
            fma2(A3a[0], t3, x2); fma2(A3a[1], t3, y2); fma2(A3a[2], t3, z2);
            const u64 t4 = mul2(w01[3], q02);
            fma2(A4a[0], t4, vx); fma2(A4a[1], t4, vy); fma2(A4a[2], t4, vz);
            fma2(A5a[0], w01[4], cx); fma2(A5a[1], w01[4], cy); fma2(A5a[2], w01[4], cz);
        }
        // pair b (channels u0+2, u0+3)
        {
            const u64 vx = VX2.y, vy = VY2.y, vz = VZ2.y, ss = S2.y;
            const u64 dot = fma2r(vx, x2, fma2r(vy, y2, mul2(vz, z2)));
            const u64 cx = fma2r(vz, ny2, mul2(vy, z2));
            const u64 cy = fma2r(vx, nz2, mul2(vz, x2));
            const u64 cz = fma2r(vy, nx2, mul2(vx, y2));
            const u64 t1 = mul2(w23[0], ss);
            fma2(A1b, t1, q02);
            fma2(A2b, w23[1], dot);
            const u64 t3 = mul2(w23[2], ss);
            fma2(A3b[0], t3, x2); fma2(A3b[1], t3, y2); fma2(A3b[2], t3, z2);
            const u64 t4 = mul2(w23[3], q02);
            fma2(A4b[0], t4, vx); fma2(A4b[1], t4, vy); fma2(A4b[2], t4, vz);
            fma2(A5b[0], w23[4], cx); fma2(A5b[1], w23[4], cy); fma2(A5b[2], w23[4], cz);
        }
    }

    // ---- butterfly reduce across the 4 edge slots (xor 8, xor 16) ----
#define RED2(v) \
    v = add2(v, __shfl_xor_sync(0xffffffffu, v, 8));  \
    v = add2(v, __shfl_xor_sync(0xffffffffu, v, 16));
    RED2(A1a) RED2(A1b) RED2(A2a) RED2(A2b)
#pragma unroll
    for (int c = 0; c < 3; c++) {
        RED2(A3a[c]) RED2(A3b[c])
        RED2(A4a[c]) RED2(A4b[c])
        RED2(A5a[c]) RED2(A5b[c])
    }
#undef RED2

    if (es == 0) {
        *reinterpret_cast<ulonglong2*>(g_aggs + n * 64 + u0)      = make_ulonglong2(A1a, A1b);
        *reinterpret_cast<ulonglong2*>(g_aggs + n * 64 + 32 + u0) = make_ulonglong2(A2a, A2b);
#pragma unroll
        for (int c = 0; c < 3; c++) {
            float* av_base = g_aggv + n * 288 + c * 96 + u0;
            *reinterpret_cast<ulonglong2*>(av_base)      = make_ulonglong2(A3a[c], A3b[c]);
            *reinterpret_cast<ulonglong2*>(av_base + 32) = make_ulonglong2(A4a[c], A4b[c]);
            *reinterpret_cast<ulonglong2*>(av_base + 64) = make_ulonglong2(A5a[c], A5b[c]);
        }
    }
}

// ---------------------------------------------------------------------------
// Scalar output: agg_s @ W2s + scalar self-connection.
// 2 NODES x 8 CHANNELS per thread.
// ---------------------------------------------------------------------------
__global__ __launch_bounds__(256) void node_s_kernel(
        const float* __restrict__ node_s,
        const float* __restrict__ attrs,
        const float* __restrict__ W2s,
        const float* __restrict__ Wscs,
        float* __restrict__ out) {
    extern __shared__ float sw[];
    float* sW2s  = sw;          // 2048 floats
    float* sWscs = sw + 2048;   // 8192 floats
    for (int i = threadIdx.x; i < 2048; i += blockDim.x)
        sW2s[i] = W2s[i] * MS_SCALE;
    for (int i = threadIdx.x; i < 8192; i += blockDim.x)
        sWscs[i] = Wscs[i] * NSC_SCALE;
    __syncthreads();

    const int gt = blockIdx.x * blockDim.x + threadIdx.x;
    const int pair = gt >> 2;
    if (pair >= N_NODES / 2) return;
    const int ch0 = (gt & 3) * 8;
    const int n0 = pair * 2;
    const int n1 = n0 + 1;

    float acc0[8], acc1[8];
#pragma unroll
    for (int j = 0; j < 8; j++) { acc0[j] = 0.f; acc1[j] = 0.f; }

    const float4* inA = reinterpret_cast<const float4*>(g_aggs + n0 * 64);
    const float4* inB = reinterpret_cast<const float4*>(g_aggs + n1 * 64);
#pragma unroll 4
    for (int k4 = 0; k4 < 16; k4++) {
        const float4 av = inA[k4];
        const float4 bv = inB[k4];
        const float a[4] = {av.x, av.y, av.z, av.w};
        const float b[4] = {bv.x, bv.y, bv.z, bv.w};
#pragma unroll
        for (int j = 0; j < 4; j++) {
            const float4* wr = reinterpret_cast<const float4*>(sW2s + (k4 * 4 + j) * 32 + ch0);
            const float4 w0 = wr[0];
            const float4 w1 = wr[1];
            acc0[0] += a[j] * w0.x; acc0[1] += a[j] * w0.y;
            acc0[2] += a[j] * w0.z; acc0[3] += a[j] * w0.w;
            acc0[4] += a[j] * w1.x; acc0[5] += a[j] * w1.y;
            acc0[6] += a[j] * w1.z; acc0[7] += a[j] * w1.w;
            acc1[0] += b[j] * w0.x; acc1[1] += b[j] * w0.y;
            acc1[2] += b[j] * w0.z; acc1[3] += b[j] * w0.w;
            acc1[4] += b[j] * w1.x; acc1[5] += b[j] * w1.y;
            acc1[6] += b[j] * w1.z; acc1[7] += b[j] * w1.w;
        }
    }

    float at0[8], at1[8];
    {
        const float4 a0 = *reinterpret_cast<const float4*>(attrs + n0 * 8);
        const float4 a1 = *reinterpret_cast<const float4*>(attrs + n0 * 8 + 4);
        at0[0]=a0.x; at0[1]=a0.y; at0[2]=a0.z; at0[3]=a0.w;
        at0[4]=a1.x; at0[5]=a1.y; at0[6]=a1.z; at0[7]=a1.w;
        const float4 b0 = *reinterpret_cast<const float4*>(attrs + n1 * 8);
        const float4 b1 = *reinterpret_cast<const float4*>(attrs + n1 * 8 + 4);
        at1[0]=b0.x; at1[1]=b0.y; at1[2]=b0.z; at1[3]=b0.w;
        at1[4]=b1.x; at1[5]=b1.y; at1[6]=b1.z; at1[7]=b1.w;
    }
    const float4* nsA = reinterpret_cast<const float4*>(node_s + n0 * 32);
    const float4* nsB = reinterpret_cast<const float4*>(node_s + n1 * 32);
#pragma unroll 2
    for (int u4 = 0; u4 < 8; u4++) {
        const float4 sa = nsA[u4];
        const float4 sb = nsB[u4];
        const float sua[4] = {sa.x, sa.y, sa.z, sa.w};
        const float sub_[4] = {sb.x, sb.y, sb.z, sb.w};
#pragma unroll
        for (int j = 0; j < 4; j++) {
            const int u = u4 * 4 + j;
#pragma unroll
            for (int a = 0; a < 8; a++) {
                const float za = sua[j] * at0[a];
                const float zb = sub_[j] * at1[a];
                const float4* wr = reinterpret_cast<const float4*>(sWscs + (u * 8 + a) * 32 + ch0);
                const float4 w0 = wr[0];
                const float4 w1 = wr[1];
                acc0[0] += za * w0.x; acc0[1] += za * w0.y;
                acc0[2] += za * w0.z; acc0[3] += za * w0.w;
                acc0[4] += za * w1.x; acc0[5] += za * w1.y;
                acc0[6] += za * w1.z; acc0[7] += za * w1.w;
                acc1[0] += zb * w0.x; acc1[1] += zb * w0.y;
                acc1[2] += zb * w0.z; acc1[3] += zb * w0.w;
                acc1[4] += zb * w1.x; acc1[5] += zb * w1.y;
                acc1[6] += zb * w1.z; acc1[7] += zb * w1.w;
            }
        }
    }

    float4* o0 = reinterpret_cast<float4*>(out + n0 * 128 + ch0);
    o0[0] = make_float4(acc0[0], acc0[1], acc0[2], acc0[3]);
    o0[1] = make_float4(acc0[4], acc0[5], acc0[6], acc0[7]);
    float4* o1 = reinterpret_cast<float4*>(out + n1 * 128 + ch0);
    o1[0] = make_float4(acc1[0], acc1[1], acc1[2], acc1[3]);
    o1[1] = make_float4(acc1[4], acc1[5], acc1[6], acc1[7]);
}

// ---------------------------------------------------------------------------
// Vector output: agg_v @ W2v + vector self-connection.
// 2 NODES x 4 CHANNELS per thread; weight LDS.128 reused across 3 comps x 2 nodes.
// ---------------------------------------------------------------------------
__global__ __launch_bounds__(256) void node_v_kernel(
        const float* __restrict__ node_v,
        const float* __restrict__ attrs,
        const float* __restrict__ W2v,
        const float* __restrict__ Wscv,
        float* __restrict__ out) {
    extern __shared__ float sw[];
    float* sW2v  = sw;          // 3072 floats
    float* sWscv = sw + 3072;   // 8192 floats
    for (int i = threadIdx.x; i < 3072; i += blockDim.x)
        sW2v[i] = W2v[i] * MV_SCALE;
    for (int i = threadIdx.x; i < 8192; i += blockDim.x)
        sWscv[i] = Wscv[i] * NSC_SCALE;
    __syncthreads();

    const int gt = blockIdx.x * blockDim.x + threadIdx.x;
    const int pair = gt >> 3;
    if (pair >= N_NODES / 2) return;
    const int ch0 = (gt & 7) * 4;
    const int n0 = pair * 2;
    const int n1 = n0 + 1;

    float accv0[3][4], accv1[3][4];
#pragma unroll
    for (int c = 0; c < 3; c++)
#pragma unroll
        for (int j = 0; j < 4; j++) { accv0[c][j] = 0.f; accv1[c][j] = 0.f; }

    const float4* iA0 = reinterpret_cast<const float4*>(g_aggv + n0 * 288);
    const float4* iA1 = reinterpret_cast<const float4*>(g_aggv + n0 * 288 + 96);
    const float4* iA2 = reinterpret_cast<const float4*>(g_aggv + n0 * 288 + 192);
    const float4* iB0 = reinterpret_cast<const float4*>(g_aggv + n1 * 288);
    const float4* iB1 = reinterpret_cast<const float4*>(g_aggv + n1 * 288 + 96);
    const float4* iB2 = reinterpret_cast<const float4*>(g_aggv + n1 * 288 + 192);
#pragma unroll 2
    for (int k4 = 0; k4 < 24; k4++) {
        const float4 a0 = iA0[k4], a1 = iA1[k4], a2 = iA2[k4];
        const float4 b0 = iB0[k4], b1 = iB1[k4], b2 = iB2[k4];
        const float fa0[4] = {a0.x, a0.y, a0.z, a0.w};
        const float fa1[4] = {a1.x, a1.y, a1.z, a1.w};
        const float fa2[4] = {a2.x, a2.y, a2.z, a2.w};
        const float fb0[4] = {b0.x, b0.y, b0.z, b0.w};
        const float fb1[4] = {b1.x, b1.y, b1.z, b1.w};
        const float fb2[4] = {b2.x, b2.y, b2.z, b2.w};
#pragma unroll
        for (int j = 0; j < 4; j++) {
            const float4 w = *reinterpret_cast<const float4*>(sW2v + (k4 * 4 + j) * 32 + ch0);
            accv0[0][0] += fa0[j] * w.x; accv0[0][1] += fa0[j] * w.y;
            accv0[0][2] += fa0[j] * w.z; accv0[0][3] += fa0[j] * w.w;
            accv0[1][0] += fa1[j] * w.x; accv0[1][1] += fa1[j] * w.y;
            accv0[1][2] += fa1[j] * w.z; accv0[1][3] += fa1[j] * w.w;
            accv0[2][0] += fa2[j] * w.x; accv0[2][1] += fa2[j] * w.y;
            accv0[2][2] += fa2[j] * w.z; accv0[2][3] += fa2[j] * w.w;
            accv1[0][0] += fb0[j] * w.x; accv1[0][1] += fb0[j] * w.y;
            accv1[0][2] += fb0[j] * w.z; accv1[0][3] += fb0[j] * w.w;
            accv1[1][0] += fb1[j] * w.x; accv1[1][1] += fb1[j] * w.y;
            accv1[1][2] += fb1[j] * w.z; accv1[1][3] += fb1[j] * w.w;
            accv1[2][0] += fb2[j] * w.x; accv1[2][1] += fb2[j] * w.y;
            accv1[2][2] += fb2[j] * w.z; accv1[2][3] += fb2[j] * w.w;
        }
    }

    float at0[8], at1[8];
    {
        const float4 a0 = *reinterpret_cast<const float4*>(attrs + n0 * 8);
        const float4 a1 = *reinterpret_cast<const float4*>(attrs + n0 * 8 + 4);
        at0[0]=a0.x; at0[1]=a0.y; at0[2]=a0.z; at0[3]=a0.w;
        at0[4]=a1.x; at0[5]=a1.y; at0[6]=a1.z; at0[7]=a1.w;
        const float4 b0 = *reinterpret_cast<const float4*>(attrs + n1 * 8);
        const float4 b1 = *reinterpret_cast<const float4*>(attrs + n1 * 8 + 4);
        at1[0]=b0.x; at1[1]=b0.y; at1[2]=b0.z; at1[3]=b0.w;
        at1[4]=b1.x; at1[5]=b1.y; at1[6]=b1.z; at1[7]=b1.w;
    }
    const float* nvA = node_v + n0 * 96;
    const float* nvB = node_v + n1 * 96;
#pragma unroll 2
    for (int u = 0; u < 32; u++) {
        float mv0[4] = {0.f, 0.f, 0.f, 0.f};
        float mv1[4] = {0.f, 0.f, 0.f, 0.f};
#pragma unroll
        for (int a = 0; a < 8; a++) {
            const float4 w = *reinterpret_cast<const float4*>(sWscv + (u * 8 + a) * 32 + ch0);
            const float wa0 = at0[a];
            const float wa1 = at1[a];
            mv0[0] += wa0 * w.x; mv0[1] += wa0 * w.y;
            mv0[2] += wa0 * w.z; mv0[3] += wa0 * w.w;
            mv1[0] += wa1 * w.x; mv1[1] += wa1 * w.y;
            mv1[2] += wa1 * w.z; mv1[3] += wa1 * w.w;
        }
        const float va0 = nvA[u * 3 + 0], va1 = nvA[u * 3 + 1], va2 = nvA[u * 3 + 2];
        const float vb0 = nvB[u * 3 + 0], vb1 = nvB[u * 3 + 1], vb2 = nvB[u * 3 + 2];
#pragma unroll
        for (int j = 0; j < 4; j++) {
            accv0[0][j] += va0 * mv0[j];
            accv0[1][j] += va1 * mv0[j];
            accv0[2][j] += va2 * mv0[j];
            accv1[0][j] += vb0 * mv1[j];
            accv1[1][j] += vb1 * mv1[j];
            accv1[2][j] += vb2 * mv1[j];
        }
    }

    {
        float4* o4 = reinterpret_cast<float4*>(out + n0 * 128 + 32 + ch0 * 3);
#pragma unroll
        for (int g = 0; g < 3; g++) {
            const int f0 = g * 4;
            float4 o;
            o.x = accv0[(f0 + 0) % 3][(f0 + 0) / 3];
            o.y = accv0[(f0 + 1) % 3][(f0 + 1) / 3];
            o.z = accv0[(f0 + 2) % 3][(f0 + 2) / 3];
            o.w = accv0[(f0 + 3) % 3][(f0 + 3) / 3];
            o4[g] = o;
        }
    }
    {
        float4* o4 = reinterpret_cast<float4*>(out + n1 * 128 + 32 + ch0 * 3);
#pragma unroll
        for (int g = 0; g < 3; g++) {
            const int f0 = g * 4;
            float4 o;
            o.x = accv1[(f0 + 0) % 3][(f0 + 0) / 3];
            o.y = accv1[(f0 + 1) % 3][(f0 + 1) / 3];
            o.z = accv1[(f0 + 2) % 3][(f0 + 2) / 3];
            o.w = accv1[(f0 + 3) % 3][(f0 + 3) / 3];
            o4[g] = o;
        }
    }
}

// ---------------------------------------------------------------------------
extern "C" void kernel_launch(void* const* d_in, const int* in_sizes, int n_in,
                              void* d_out, int out_size) {
    const float* node_s     = (const float*)d_in[0];
    const float* node_v     = (const float*)d_in[1];
    const float* node_attrs = (const float*)d_in[2];
    const float* edge_emb   = (const float*)d_in[3];
    const float* edge_sh0   = (const float*)d_in[4];
    const float* edge_sh1   = (const float*)d_in[5];
    const float* W1_s       = (const float*)d_in[6];
    const float* W1_v       = (const float*)d_in[7];
    const float* Wm1        = (const float*)d_in[8];
    const float* Wm2        = (const float*)d_in[9];
    const float* W2_s       = (const float*)d_in[10];
    const float* W2_v       = (const float*)d_in[11];
    const float* Wsc_s      = (const float*)d_in[12];
    const float* Wsc_v      = (const float*)d_in[13];
    const int*   edge_src   = (const int*)d_in[14];
    const int*   edge_dst   = (const int*)d_in[15];
    float* out = (float*)d_out;

    // CSR build + payload permutation (by destination)
    zero_cnt_kernel<<<(N_NODES + 255) / 256, 256>>>();
    count_kernel<<<(N_EDGES + 255) / 256, 256>>>(edge_dst);
    scan_kernel<<<1, 1024>>>();
    fill_kernel<<<(N_EDGES + 255) / 256, 256>>>(edge_dst, edge_src,
                                                edge_emb, edge_sh0, edge_sh1);

    // linear_1 (independent of CSR)
    lin1_kernel<<<(N_NODES + 7) / 8, 256>>>(node_s, node_v, W1_s, W1_v);

    // warp-per-node gather + tensor product (no atomics, f32x2 packed)
    gather_tp<<<(N_NODES * 32 + 255) / 256, 256>>>(Wm1, Wm2);

    // linear_2 + self-connection
    node_s_kernel<<<(N_NODES / 2 * 4 + 255) / 256, 256, 10240 * sizeof(float)>>>(
        node_s, node_attrs, W2_s, Wsc_s, out);
    node_v_kernel<<<(N_NODES / 2 * 8 + 255) / 256, 256, 11264 * sizeof(float)>>>(
        node_v, node_attrs, W2_v, Wsc_v, out);
}